// round 1
// baseline (speedup 1.0000x reference)
#include <cuda_runtime.h>

// Problem constants (fixed shapes from setup_inputs)
#define T_STEPS 32
#define BATCH   128
#define DIN     2048
#define DOUT    2048
#define M_ROWS  (T_STEPS * BATCH)   // 4096

// SGEMM tile config
#define BM 128
#define BN 128
#define BK 16
#define NTHREADS 256

// Scratch for X = cur_inp @ W^T  (no bias), [M_ROWS, DOUT] row-major.
__device__ float g_X[(size_t)M_ROWS * DOUT];

// ---------------------------------------------------------------------------
// fp32 SGEMM (NT: both operands K-contiguous):
//   X[m, n] = sum_k A[m, k] * W[n, k]
// Classic 128x128x16 tiling, 8x8 per thread, double-buffered shared memory,
// transposed smem staging for conflict-free vectorized compute loads.
// ---------------------------------------------------------------------------
__global__ __launch_bounds__(NTHREADS, 2)
void sgemm_nt_kernel(const float* __restrict__ A,
                     const float* __restrict__ W,
                     float* __restrict__ X)
{
    __shared__ float As[2][BK][BM];
    __shared__ float Bs[2][BK][BN];

    const int tid = threadIdx.x;
    const int bx  = blockIdx.x;   // N tile index
    const int by  = blockIdx.y;   // M tile index

    const float* Ab = A + (size_t)by * BM * DIN;
    const float* Wb = W + (size_t)bx * BN * DIN;

    // Global->shared loader mapping: 512 float4 per tile, 2 per thread.
    const int lr0 = tid >> 2;           // row 0..63
    const int lc0 = (tid & 3) * 4;      // k-col within tile: 0,4,8,12
    // second load: row lr0+64, same k-col

    float4 pa0, pa1, pb0, pb1;

    // compute mapping
    const int tx = tid & 15;
    const int ty = tid >> 4;
    const int r0 = ty * 4;              // rows r0..r0+3 and r0+64..r0+67
    const int c0 = tx * 4;              // cols c0..c0+3 and c0+64..c0+67

    float acc[8][8];
#pragma unroll
    for (int i = 0; i < 8; ++i)
#pragma unroll
        for (int j = 0; j < 8; ++j) acc[i][j] = 0.f;

    // --- initial global load (k0 = 0) ---
    {
        const int k0 = 0;
        pa0 = *(const float4*)(Ab + (size_t)lr0 * DIN + k0 + lc0);
        pa1 = *(const float4*)(Ab + (size_t)(lr0 + 64) * DIN + k0 + lc0);
        pb0 = *(const float4*)(Wb + (size_t)lr0 * DIN + k0 + lc0);
        pb1 = *(const float4*)(Wb + (size_t)(lr0 + 64) * DIN + k0 + lc0);
    }
    // store tile 0 into buffer 0 (transposed: smem[k][m])
    {
        As[0][lc0 + 0][lr0] = pa0.x; As[0][lc0 + 1][lr0] = pa0.y;
        As[0][lc0 + 2][lr0] = pa0.z; As[0][lc0 + 3][lr0] = pa0.w;
        As[0][lc0 + 0][lr0 + 64] = pa1.x; As[0][lc0 + 1][lr0 + 64] = pa1.y;
        As[0][lc0 + 2][lr0 + 64] = pa1.z; As[0][lc0 + 3][lr0 + 64] = pa1.w;
        Bs[0][lc0 + 0][lr0] = pb0.x; Bs[0][lc0 + 1][lr0] = pb0.y;
        Bs[0][lc0 + 2][lr0] = pb0.z; Bs[0][lc0 + 3][lr0] = pb0.w;
        Bs[0][lc0 + 0][lr0 + 64] = pb1.x; Bs[0][lc0 + 1][lr0 + 64] = pb1.y;
        Bs[0][lc0 + 2][lr0 + 64] = pb1.z; Bs[0][lc0 + 3][lr0 + 64] = pb1.w;
    }
    __syncthreads();

    const int nT = DIN / BK;   // 128
    for (int t = 0; t < nT; ++t) {
        const int buf = t & 1;

        // prefetch next tile from global into registers
        if (t + 1 < nT) {
            const int k0 = (t + 1) * BK;
            pa0 = *(const float4*)(Ab + (size_t)lr0 * DIN + k0 + lc0);
            pa1 = *(const float4*)(Ab + (size_t)(lr0 + 64) * DIN + k0 + lc0);
            pb0 = *(const float4*)(Wb + (size_t)lr0 * DIN + k0 + lc0);
            pb1 = *(const float4*)(Wb + (size_t)(lr0 + 64) * DIN + k0 + lc0);
        }

        // compute on current buffer
#pragma unroll
        for (int kk = 0; kk < BK; ++kk) {
            float4 a0 = *(const float4*)&As[buf][kk][r0];
            float4 a1 = *(const float4*)&As[buf][kk][r0 + 64];
            float4 b0 = *(const float4*)&Bs[buf][kk][c0];
            float4 b1 = *(const float4*)&Bs[buf][kk][c0 + 64];
            float a[8] = {a0.x, a0.y, a0.z, a0.w, a1.x, a1.y, a1.z, a1.w};
            float b[8] = {b0.x, b0.y, b0.z, b0.w, b1.x, b1.y, b1.z, b1.w};
#pragma unroll
            for (int i = 0; i < 8; ++i)
#pragma unroll
                for (int j = 0; j < 8; ++j)
                    acc[i][j] += a[i] * b[j];
        }

        // stage prefetched tile into the other buffer
        if (t + 1 < nT) {
            const int nb = buf ^ 1;
            As[nb][lc0 + 0][lr0] = pa0.x; As[nb][lc0 + 1][lr0] = pa0.y;
            As[nb][lc0 + 2][lr0] = pa0.z; As[nb][lc0 + 3][lr0] = pa0.w;
            As[nb][lc0 + 0][lr0 + 64] = pa1.x; As[nb][lc0 + 1][lr0 + 64] = pa1.y;
            As[nb][lc0 + 2][lr0 + 64] = pa1.z; As[nb][lc0 + 3][lr0 + 64] = pa1.w;
            Bs[nb][lc0 + 0][lr0] = pb0.x; Bs[nb][lc0 + 1][lr0] = pb0.y;
            Bs[nb][lc0 + 2][lr0] = pb0.z; Bs[nb][lc0 + 3][lr0] = pb0.w;
            Bs[nb][lc0 + 0][lr0 + 64] = pb1.x; Bs[nb][lc0 + 1][lr0 + 64] = pb1.y;
            Bs[nb][lc0 + 2][lr0 + 64] = pb1.z; Bs[nb][lc0 + 3][lr0 + 64] = pb1.w;
        }
        __syncthreads();
    }

    // epilogue: write 8x8 accumulators as float4 pairs
#pragma unroll
    for (int i = 0; i < 8; ++i) {
        const int lrow = (i < 4) ? (r0 + i) : (r0 + 64 + (i - 4));
        float* xr = X + (size_t)(by * BM + lrow) * DOUT + bx * BN;
        *(float4*)(xr + c0)      = make_float4(acc[i][0], acc[i][1], acc[i][2], acc[i][3]);
        *(float4*)(xr + c0 + 64) = make_float4(acc[i][4], acc[i][5], acc[i][6], acc[i][7]);
    }
}

// ---------------------------------------------------------------------------
// IF-neuron scan over T=32 steps per (b, o) element.
// mem = mem*(1-spike) + (x + bias);  spike = mem > 1;  out = sum(spike)/T.
// ---------------------------------------------------------------------------
__global__ void if_scan_kernel(const float* __restrict__ X,
                               const float* __restrict__ bias,
                               const float* __restrict__ mem_init,
                               float* __restrict__ out)
{
    const int idx = blockIdx.x * blockDim.x + threadIdx.x;  // over BATCH*DOUT
    const int o = idx & (DOUT - 1);
    const int b = idx >> 11;   // / DOUT

    const float bi   = bias[o];
    float mem        = mem_init[idx];
    float spike      = 0.f;
    float acc        = 0.f;

#pragma unroll
    for (int t = 0; t < T_STEPS; ++t) {
        const float x = X[((size_t)t * BATCH + b) * DOUT + o] + bi;
        mem = mem * (1.f - spike) + x;
        spike = (mem > 1.f) ? 1.f : 0.f;
        acc += spike;
    }
    out[idx] = acc * (1.f / (float)T_STEPS);   // * VTH / T, VTH = 1
}

// ---------------------------------------------------------------------------
extern "C" void kernel_launch(void* const* d_in, const int* in_sizes, int n_in,
                              void* d_out, int out_size)
{
    const float* cur_inp  = (const float*)d_in[0];  // [T, B, DIN]
    const float* weight   = (const float*)d_in[1];  // [DOUT, DIN]
    const float* bias     = (const float*)d_in[2];  // [DOUT]
    const float* mem_init = (const float*)d_in[3];  // [B, DOUT]
    float* out = (float*)d_out;                     // [B, DOUT]

    float* X = nullptr;
    cudaGetSymbolAddress((void**)&X, g_X);

    dim3 grid(DOUT / BN, M_ROWS / BM);   // (16, 32)
    sgemm_nt_kernel<<<grid, NTHREADS>>>(cur_inp, weight, X);

    const int total = BATCH * DOUT;      // 262144
    if_scan_kernel<<<total / 256, 256>>>(X, bias, mem_init, out);
}

// round 5
// speedup vs baseline: 1.2362x; 1.2362x over previous
#include <cuda_runtime.h>
#include <cstdint>

// ---------------------------------------------------------------------------
// Problem constants (fixed shapes)
// ---------------------------------------------------------------------------
#define T_STEPS 32
#define BATCH   128
#define DIN     2048
#define DOUT    2048
#define M_ROWS  (T_STEPS * BATCH)   // 4096

#define NCHUNKS (DIN / 16)          // 128 k-chunks of 16
#define GEMM_THREADS 256
#define STAGE_FLOATS 8192           // Ahi 2048 | Alo 2048 | Bhi 2048 | Blo 2048
#define NSTAGES 4
#define SMEM_BYTES (NSTAGES * STAGE_FLOATS * 4)   // 128 KB dynamic
#define ACC_WINDOW 8                // flush HMMA accumulator every 8 chunks (K=128)

// ---------------------------------------------------------------------------
// Device scratch (permuted tf32 hi/lo operands + GEMM output)
// ---------------------------------------------------------------------------
__device__ float g_X  [(size_t)M_ROWS * DOUT];
__device__ float g_Ahi[(size_t)M_ROWS * DIN];
__device__ float g_Alo[(size_t)M_ROWS * DIN];
__device__ float g_Whi[(size_t)DOUT * DIN];
__device__ float g_Wlo[(size_t)DOUT * DIN];

// ---------------------------------------------------------------------------
// Helpers
// ---------------------------------------------------------------------------
__device__ __forceinline__ uint32_t smem_u32(const void* p) {
    uint32_t a;
    asm("{ .reg .u64 t; cvta.to.shared.u64 t, %1; cvt.u32.u64 %0, t; }"
        : "=r"(a) : "l"(p));
    return a;
}

__device__ __forceinline__ void cp16(uint32_t sm, const void* gp) {
    asm volatile("cp.async.cg.shared.global [%0], [%1], 16;"
                 :: "r"(sm), "l"(gp) : "memory");
}

__device__ __forceinline__ float tf32_rna(float a) {
    uint32_t r;
    asm("cvt.rna.tf32.f32 %0, %1;" : "=r"(r) : "f"(a));
    return __uint_as_float(r);
}

__device__ __forceinline__ void mma_m16n8k8(float* c, const uint32_t* a,
                                            const uint32_t* b) {
    asm volatile(
        "mma.sync.aligned.m16n8k8.row.col.f32.tf32.tf32.f32 "
        "{%0,%1,%2,%3}, {%4,%5,%6,%7}, {%8,%9}, {%0,%1,%2,%3};"
        : "+f"(c[0]), "+f"(c[1]), "+f"(c[2]), "+f"(c[3])
        : "r"(a[0]), "r"(a[1]), "r"(a[2]), "r"(a[3]), "r"(b[0]), "r"(b[1]));
}

// ---------------------------------------------------------------------------
// Split+permute kernels.
// A_perm (per hi/lo): idx = (mblk*NCHUNKS + chunk)*2048 + ((mt*2+kt)*32+lane)*4 + reg
//   where lane = rr*4+kl (rr = fragment row 0..7, kl = frag col 0..3),
//   reg r -> (i = r&1, j = r>>1): m = mblk*128+mt*16+i*8+rr, k = chunk*16+kt*8+j*4+kl
// ---------------------------------------------------------------------------
__global__ void splitA_kernel(const float* __restrict__ A,
                              float4* __restrict__ hi, float4* __restrict__ lo) {
    const int q = blockIdx.x * blockDim.x + threadIdx.x;   // 2097152 groups
    const int lane  = q & 31;
    const int kt    = (q >> 5) & 1;
    const int mt    = (q >> 6) & 7;
    const int chunk = (q >> 9) & (NCHUNKS - 1);
    const int mblk  = q >> 16;

    const int rr = lane >> 2, kl = lane & 3;
    const int m0 = mblk * 128 + mt * 16 + rr;
    const int k0 = chunk * 16 + kt * 8 + kl;

    const float a00 = A[(size_t)m0 * DIN + k0];
    const float a10 = A[(size_t)(m0 + 8) * DIN + k0];
    const float a01 = A[(size_t)m0 * DIN + k0 + 4];
    const float a11 = A[(size_t)(m0 + 8) * DIN + k0 + 4];

    float4 h, l;
    h.x = tf32_rna(a00); l.x = tf32_rna(a00 - h.x);
    h.y = tf32_rna(a10); l.y = tf32_rna(a10 - h.y);
    h.z = tf32_rna(a01); l.z = tf32_rna(a01 - h.z);
    h.w = tf32_rna(a11); l.w = tf32_rna(a11 - h.w);
    hi[q] = h;
    lo[q] = l;
}

// B_perm: idx = (nblk*NCHUNKS + chunk)*2048 + (nt*32+lane)*4 + reg
//   lane = nr*4+kl; value reg r = W[nblk*128+nt*8+nr, chunk*16 + r*4 + kl]
__global__ void splitB_kernel(const float* __restrict__ W,
                              float4* __restrict__ hi, float4* __restrict__ lo) {
    const int q = blockIdx.x * blockDim.x + threadIdx.x;   // 1048576 groups
    const int lane  = q & 31;
    const int nt    = (q >> 5) & 15;
    const int chunk = (q >> 9) & (NCHUNKS - 1);
    const int nblk  = q >> 16;

    const int nr = lane >> 2, kl = lane & 3;
    const int n  = nblk * 128 + nt * 8 + nr;
    const int k0 = chunk * 16 + kl;

    const float b0 = W[(size_t)n * DIN + k0];
    const float b1 = W[(size_t)n * DIN + k0 + 4];
    const float b2 = W[(size_t)n * DIN + k0 + 8];
    const float b3 = W[(size_t)n * DIN + k0 + 12];

    float4 h, l;
    h.x = tf32_rna(b0); l.x = tf32_rna(b0 - h.x);
    h.y = tf32_rna(b1); l.y = tf32_rna(b1 - h.y);
    h.z = tf32_rna(b2); l.z = tf32_rna(b2 - h.z);
    h.w = tf32_rna(b3); l.w = tf32_rna(b3 - h.w);
    hi[q] = h;
    lo[q] = l;
}

// ---------------------------------------------------------------------------
// 3xTF32 GEMM via mma.sync: X[m,n] = sum_k A[m,k] * W[n,k]
// CTA tile 128x128, 8 warps (2x4), warp tile 64x32, BK=16, 4-stage cp.async.
// Two-level accumulation: HMMA window accumulator (RZ-biased chain bounded to
// ACC_WINDOW chunks) flushed into a master fp32 accumulator with RN FADDs.
// ---------------------------------------------------------------------------
__global__ __launch_bounds__(GEMM_THREADS, 1)
void gemm_tf32x3_kernel(const float* __restrict__ Ahi, const float* __restrict__ Alo,
                        const float* __restrict__ Bhi, const float* __restrict__ Blo,
                        float* __restrict__ X)
{
    extern __shared__ __align__(16) float smem[];   // NSTAGES * STAGE_FLOATS

    const int tid  = threadIdx.x;
    const int wid  = tid >> 5;
    const int lane = tid & 31;
    const int bx = blockIdx.x;          // N block (0..15)
    const int by = blockIdx.y;          // M block (0..31)
    const int wr = wid >> 2;            // warp row (0..1)
    const int wc = wid & 3;             // warp col (0..3)

    const uint32_t sbase = smem_u32(smem);

    // cp.async staging: one chunk = 4 regions x 8KB, fully linear copies.
    auto issue = [&](int c, int s) {
        const uint32_t sb = sbase + (uint32_t)s * (STAGE_FLOATS * 4);
        const size_t aoff = ((size_t)(by * NCHUNKS + c)) * 2048;
        const size_t boff = ((size_t)(bx * NCHUNKS + c)) * 2048;
#pragma unroll
        for (int j = 0; j < 2; ++j) {
            const int t16 = tid + j * 256;      // 16B-chunk id (0..511)
            cp16(sb + 0     + t16 * 16, Ahi + aoff + t16 * 4);
            cp16(sb + 8192  + t16 * 16, Alo + aoff + t16 * 4);
            cp16(sb + 16384 + t16 * 16, Bhi + boff + t16 * 4);
            cp16(sb + 24576 + t16 * 16, Blo + boff + t16 * 4);
        }
        asm volatile("cp.async.commit_group;" ::: "memory");
    };

    float acc[4][4][4];    // master (RN adds only)
    float macc[4][4][4];   // HMMA window accumulator
#pragma unroll
    for (int i = 0; i < 4; ++i)
#pragma unroll
        for (int j = 0; j < 4; ++j)
#pragma unroll
            for (int r = 0; r < 4; ++r) acc[i][j][r] = 0.f;

    // prologue: stages 0..2
    issue(0, 0);
    issue(1, 1);
    issue(2, 2);

    for (int i = 0; i < NCHUNKS; ++i) {
        asm volatile("cp.async.wait_group 2;" ::: "memory");
        __syncthreads();

        // keep exactly one commit per iteration (empty groups complete instantly)
        if (i + 3 < NCHUNKS) issue(i + 3, (i + 3) & (NSTAGES - 1));
        else asm volatile("cp.async.commit_group;" ::: "memory");

        const float* st = smem + (i & (NSTAGES - 1)) * STAGE_FLOATS;

        // window start: reset HMMA accumulator
        if ((i & (ACC_WINDOW - 1)) == 0) {
#pragma unroll
            for (int mt = 0; mt < 4; ++mt)
#pragma unroll
                for (int nt = 0; nt < 4; ++nt)
#pragma unroll
                    for (int r = 0; r < 4; ++r) macc[mt][nt][r] = 0.f;
        }

        // B fragments for both k-steps: regs {2kt, 2kt+1}
        uint32_t b[2][4][4];
#pragma unroll
        for (int nt = 0; nt < 4; ++nt) {
            const int ntg = wc * 4 + nt;
            *(float4*)&b[0][nt][0] = *(const float4*)&st[4096 + (ntg * 32 + lane) * 4];
            *(float4*)&b[1][nt][0] = *(const float4*)&st[6144 + (ntg * 32 + lane) * 4];
        }

#pragma unroll
        for (int kt = 0; kt < 2; ++kt) {
            uint32_t a[2][4][4];
#pragma unroll
            for (int mt = 0; mt < 4; ++mt) {
                const int mtg = wr * 4 + mt;
                *(float4*)&a[0][mt][0] =
                    *(const float4*)&st[((mtg * 2 + kt) * 32 + lane) * 4];
                *(float4*)&a[1][mt][0] =
                    *(const float4*)&st[2048 + ((mtg * 2 + kt) * 32 + lane) * 4];
            }
#pragma unroll
            for (int mt = 0; mt < 4; ++mt)
#pragma unroll
                for (int nt = 0; nt < 4; ++nt) {
                    mma_m16n8k8(macc[mt][nt], a[0][mt], &b[0][nt][2 * kt]); // hi*hi
                    mma_m16n8k8(macc[mt][nt], a[0][mt], &b[1][nt][2 * kt]); // hi*lo
                    mma_m16n8k8(macc[mt][nt], a[1][mt], &b[0][nt][2 * kt]); // lo*hi
                }
        }

        // window end: flush into master with RN adds
        if ((i & (ACC_WINDOW - 1)) == (ACC_WINDOW - 1)) {
#pragma unroll
            for (int mt = 0; mt < 4; ++mt)
#pragma unroll
                for (int nt = 0; nt < 4; ++nt)
#pragma unroll
                    for (int r = 0; r < 4; ++r) acc[mt][nt][r] += macc[mt][nt][r];
        }
    }

    // epilogue: C fragment (m16n8 f32): c0,c1 @ (r, 2c),(r, 2c+1); c2,c3 @ (r+8, ...)
    const int r = lane >> 2, c2 = (lane & 3) * 2;
#pragma unroll
    for (int mt = 0; mt < 4; ++mt) {
#pragma unroll
        for (int nt = 0; nt < 4; ++nt) {
            const int m = by * 128 + wr * 64 + mt * 16 + r;
            const int n = bx * 128 + wc * 32 + nt * 8 + c2;
            *(float2*)&X[(size_t)m * DOUT + n] =
                make_float2(acc[mt][nt][0], acc[mt][nt][1]);
            *(float2*)&X[(size_t)(m + 8) * DOUT + n] =
                make_float2(acc[mt][nt][2], acc[mt][nt][3]);
        }
    }
}

// ---------------------------------------------------------------------------
// IF-neuron scan: mem = mem*(1-spike) + (x + bias); spike = mem > 1
// ---------------------------------------------------------------------------
__global__ void if_scan_kernel(const float* __restrict__ X,
                               const float* __restrict__ bias,
                               const float* __restrict__ mem_init,
                               float* __restrict__ out)
{
    const int idx = blockIdx.x * blockDim.x + threadIdx.x;
    const int o = idx & (DOUT - 1);
    const int b = idx >> 11;

    const float bi = bias[o];
    float mem   = mem_init[idx];
    float spike = 0.f;
    float acc   = 0.f;

#pragma unroll
    for (int t = 0; t < T_STEPS; ++t) {
        const float x = X[((size_t)t * BATCH + b) * DOUT + o] + bi;
        mem = mem * (1.f - spike) + x;
        spike = (mem > 1.f) ? 1.f : 0.f;
        acc += spike;
    }
    out[idx] = acc * (1.f / (float)T_STEPS);
}

// ---------------------------------------------------------------------------
extern "C" void kernel_launch(void* const* d_in, const int* in_sizes, int n_in,
                              void* d_out, int out_size)
{
    const float* cur_inp  = (const float*)d_in[0];  // [T, B, DIN]
    const float* weight   = (const float*)d_in[1];  // [DOUT, DIN]
    const float* bias     = (const float*)d_in[2];  // [DOUT]
    const float* mem_init = (const float*)d_in[3];  // [B, DOUT]
    float* out = (float*)d_out;                     // [B, DOUT]

    float *X, *Ahi, *Alo, *Whi, *Wlo;
    cudaGetSymbolAddress((void**)&X,   g_X);
    cudaGetSymbolAddress((void**)&Ahi, g_Ahi);
    cudaGetSymbolAddress((void**)&Alo, g_Alo);
    cudaGetSymbolAddress((void**)&Whi, g_Whi);
    cudaGetSymbolAddress((void**)&Wlo, g_Wlo);

    cudaFuncSetAttribute(gemm_tf32x3_kernel,
                         cudaFuncAttributeMaxDynamicSharedMemorySize, SMEM_BYTES);

    // split + permute into mma fragment layout
    splitA_kernel<<<(M_ROWS * DIN / 4) / 256, 256>>>(cur_inp,
                                                     (float4*)Ahi, (float4*)Alo);
    splitB_kernel<<<(DOUT * DIN / 4) / 256, 256>>>(weight,
                                                   (float4*)Whi, (float4*)Wlo);

    // 3xTF32 tensor-core GEMM
    dim3 grid(DOUT / 128, M_ROWS / 128);   // (16, 32)
    gemm_tf32x3_kernel<<<grid, GEMM_THREADS, SMEM_BYTES>>>(Ahi, Alo, Whi, Wlo, X);

    // IF scan
    const int total = BATCH * DOUT;
    if_scan_kernel<<<total / 256, 256>>>(X, bias, mem_init, out);
}

// round 6
// speedup vs baseline: 2.0221x; 1.6358x over previous
#include <cuda_runtime.h>
#include <cuda_fp16.h>
#include <cstdint>

// ---------------------------------------------------------------------------
// Problem constants (fixed shapes)
// ---------------------------------------------------------------------------
#define T_STEPS 32
#define BATCH   128
#define DIN     2048
#define DOUT    2048
#define M_ROWS  (T_STEPS * BATCH)   // 4096

#define NCHUNKS (DIN / 16)          // 128 k-chunks of 16
#define GEMM_THREADS 256
#define STAGE_BYTES 16384           // Ahi 4K | Alo 4K | Bhi 4K | Blo 4K
#define NSTAGES 4
#define SMEM_BYTES (NSTAGES * STAGE_BYTES)   // 64 KB dynamic
#define ACC_WINDOW 8                // flush HMMA accumulator every 8 chunks (K=128)

// ---------------------------------------------------------------------------
// Device scratch (fragment-permuted fp16 hi/lo operands + GEMM output)
// A: per (mblk,chunk) region of 256 uint4; uint4 = one lane's 4 a-regs.
// B: per (nblk,chunk) region of 256 uint4; uint4 = one lane's 2 n-tiles x 2 b-regs.
// ---------------------------------------------------------------------------
__device__ float g_X [(size_t)M_ROWS * DOUT];
__device__ uint4 g_Ah[(size_t)M_ROWS * DIN / 8];
__device__ uint4 g_Al[(size_t)M_ROWS * DIN / 8];
__device__ uint4 g_Wh[(size_t)DOUT * DIN / 8];
__device__ uint4 g_Wl[(size_t)DOUT * DIN / 8];

// ---------------------------------------------------------------------------
// Helpers
// ---------------------------------------------------------------------------
__device__ __forceinline__ uint32_t smem_u32(const void* p) {
    uint32_t a;
    asm("{ .reg .u64 t; cvta.to.shared.u64 t, %1; cvt.u32.u64 %0, t; }"
        : "=r"(a) : "l"(p));
    return a;
}

__device__ __forceinline__ void cp16(uint32_t sm, const void* gp) {
    asm volatile("cp.async.cg.shared.global [%0], [%1], 16;"
                 :: "r"(sm), "l"(gp) : "memory");
}

__device__ __forceinline__ uint32_t pack2(float x, float y) {
    __half2 h = __floats2half2_rn(x, y);
    return *reinterpret_cast<uint32_t*>(&h);
}

// fp16 m16n8k16 row.col, fp32 accumulate
__device__ __forceinline__ void mma16(float* c, const uint32_t* a,
                                      const uint32_t* b) {
    asm volatile(
        "mma.sync.aligned.m16n8k16.row.col.f32.f16.f16.f32 "
        "{%0,%1,%2,%3}, {%4,%5,%6,%7}, {%8,%9}, {%0,%1,%2,%3};"
        : "+f"(c[0]), "+f"(c[1]), "+f"(c[2]), "+f"(c[3])
        : "r"(a[0]), "r"(a[1]), "r"(a[2]), "r"(a[3]), "r"(b[0]), "r"(b[1]));
}

// ---------------------------------------------------------------------------
// Split+permute kernels: a -> hi = fp16_rn(a), lo = fp16_rn(a - hi)
//
// A fragment (m16n8k16): lane = g*4+tig (g=row 0..7, tig=k-pair 0..3)
//   reg0 = A[m0+g  ][k0+tig*2, +1]   reg1 = A[m0+g+8][k0+tig*2, +1]
//   reg2 = A[m0+g  ][k0+tig*2+8,+9]  reg3 = A[m0+g+8][k0+tig*2+8,+9]
// stored at ((mblk*NCHUNKS+chunk)*256 + mtg*32 + lane)
// ---------------------------------------------------------------------------
__global__ void splitA_kernel(const float* __restrict__ A,
                              uint4* __restrict__ hi, uint4* __restrict__ lo) {
    const int q = blockIdx.x * blockDim.x + threadIdx.x;   // 1048576
    const int lane  = q & 31;
    const int mtg   = (q >> 5) & 7;
    const int chunk = (q >> 8) & (NCHUNKS - 1);
    const int mblk  = q >> 15;

    const int g = lane >> 2, tig = lane & 3;
    const int m0 = mblk * 128 + mtg * 16;
    const int k0 = chunk * 16 + tig * 2;

    const float* r0 = A + (size_t)(m0 + g) * DIN + k0;
    const float* r1 = A + (size_t)(m0 + g + 8) * DIN + k0;
    float v[8] = { r0[0], r0[1], r1[0], r1[1], r0[8], r0[9], r1[8], r1[9] };

    float h[8], l[8];
#pragma unroll
    for (int i = 0; i < 8; ++i) {
        h[i] = __half2float(__float2half_rn(v[i]));
        l[i] = v[i] - h[i];
    }
    const size_t idx = ((size_t)mblk * NCHUNKS + chunk) * 256 + mtg * 32 + lane;
    hi[idx] = make_uint4(pack2(h[0], h[1]), pack2(h[2], h[3]),
                         pack2(h[4], h[5]), pack2(h[6], h[7]));
    lo[idx] = make_uint4(pack2(l[0], l[1]), pack2(l[2], l[3]),
                         pack2(l[4], l[5]), pack2(l[6], l[7]));
}

// B fragment (m16n8k16 col): lane = g*4+tig (g = n-col 0..7)
//   reg0 = W[n][k0+tig*2, +1]   reg1 = W[n][k0+tig*2+8, +9]
// uint4 packs an n-tile pair: x,y = regs of ntg=2p; z,w = regs of ntg=2p+1
// stored at ((nblk*NCHUNKS+chunk)*256 + p*32 + lane)
__global__ void splitB_kernel(const float* __restrict__ W,
                              uint4* __restrict__ hi, uint4* __restrict__ lo) {
    const int q = blockIdx.x * blockDim.x + threadIdx.x;   // 524288
    const int lane  = q & 31;
    const int p     = (q >> 5) & 7;
    const int chunk = (q >> 8) & (NCHUNKS - 1);
    const int nblk  = q >> 15;

    const int g = lane >> 2, tig = lane & 3;
    const int n_a = nblk * 128 + p * 16 + g;      // ntg = 2p
    const int n_b = n_a + 8;                      // ntg = 2p+1
    const int k0 = chunk * 16 + tig * 2;

    const float* ra = W + (size_t)n_a * DIN + k0;
    const float* rb = W + (size_t)n_b * DIN + k0;
    float v[8] = { ra[0], ra[1], ra[8], ra[9], rb[0], rb[1], rb[8], rb[9] };

    float h[8], l[8];
#pragma unroll
    for (int i = 0; i < 8; ++i) {
        h[i] = __half2float(__float2half_rn(v[i]));
        l[i] = v[i] - h[i];
    }
    const size_t idx = ((size_t)nblk * NCHUNKS + chunk) * 256 + p * 32 + lane;
    hi[idx] = make_uint4(pack2(h[0], h[1]), pack2(h[2], h[3]),
                         pack2(h[4], h[5]), pack2(h[6], h[7]));
    lo[idx] = make_uint4(pack2(l[0], l[1]), pack2(l[2], l[3]),
                         pack2(l[4], l[5]), pack2(l[6], l[7]));
}

// ---------------------------------------------------------------------------
// fp16x3 GEMM via mma.sync.m16n8k16: X[m,n] = sum_k A[m,k] * W[n,k]
// CTA tile 128x128, 8 warps (2x4), warp tile 64x32, k-chunk 16, 4-stage
// cp.async. Windowed two-level accumulation (RZ chain bounded, RN flush).
// ---------------------------------------------------------------------------
__global__ __launch_bounds__(GEMM_THREADS, 1)
void gemm_fp16x3_kernel(const uint4* __restrict__ Ah, const uint4* __restrict__ Al,
                        const uint4* __restrict__ Bh, const uint4* __restrict__ Bl,
                        float* __restrict__ X)
{
    extern __shared__ __align__(16) char smem[];   // NSTAGES * STAGE_BYTES

    const int tid  = threadIdx.x;
    const int wid  = tid >> 5;
    const int lane = tid & 31;
    const int bx = blockIdx.x;          // N block (0..15)
    const int by = blockIdx.y;          // M block (0..31)
    const int wr = wid >> 2;            // warp row (0..1)
    const int wc = wid & 3;             // warp col (0..3)

    const uint32_t sbase = smem_u32(smem);

    // one stage = 1024 x 16B: Ahi[256] Alo[256] Bhi[256] Blo[256]
    auto issue = [&](int c, int s) {
        const uint32_t sb = sbase + (uint32_t)s * STAGE_BYTES;
        const uint4* ah = Ah + ((size_t)by * NCHUNKS + c) * 256;
        const uint4* al = Al + ((size_t)by * NCHUNKS + c) * 256;
        const uint4* bh = Bh + ((size_t)bx * NCHUNKS + c) * 256;
        const uint4* bl = Bl + ((size_t)bx * NCHUNKS + c) * 256;
        cp16(sb + 0     + tid * 16, ah + tid);
        cp16(sb + 4096  + tid * 16, al + tid);
        cp16(sb + 8192  + tid * 16, bh + tid);
        cp16(sb + 12288 + tid * 16, bl + tid);
        asm volatile("cp.async.commit_group;" ::: "memory");
    };

    float acc[4][4][4];    // master (RN adds only)
    float macc[4][4][4];   // HMMA window accumulator
#pragma unroll
    for (int i = 0; i < 4; ++i)
#pragma unroll
        for (int j = 0; j < 4; ++j)
#pragma unroll
            for (int r = 0; r < 4; ++r) acc[i][j][r] = 0.f;

    issue(0, 0);
    issue(1, 1);
    issue(2, 2);

    for (int i = 0; i < NCHUNKS; ++i) {
        asm volatile("cp.async.wait_group 2;" ::: "memory");
        __syncthreads();

        if (i + 3 < NCHUNKS) issue(i + 3, (i + 3) & (NSTAGES - 1));
        else asm volatile("cp.async.commit_group;" ::: "memory");

        const char* st = smem + (i & (NSTAGES - 1)) * STAGE_BYTES;

        if ((i & (ACC_WINDOW - 1)) == 0) {
#pragma unroll
            for (int mt = 0; mt < 4; ++mt)
#pragma unroll
                for (int nt = 0; nt < 4; ++nt)
#pragma unroll
                    for (int r = 0; r < 4; ++r) macc[mt][nt][r] = 0.f;
        }

        // B fragments: 2 n-tile pairs x 2 terms -> 4 lds.128
        uint4 bh0 = *(const uint4*)(st + 8192  + ((wc * 2 + 0) * 32 + lane) * 16);
        uint4 bh1 = *(const uint4*)(st + 8192  + ((wc * 2 + 1) * 32 + lane) * 16);
        uint4 bl0 = *(const uint4*)(st + 12288 + ((wc * 2 + 0) * 32 + lane) * 16);
        uint4 bl1 = *(const uint4*)(st + 12288 + ((wc * 2 + 1) * 32 + lane) * 16);
        uint32_t bh[4][2] = { {bh0.x, bh0.y}, {bh0.z, bh0.w},
                              {bh1.x, bh1.y}, {bh1.z, bh1.w} };
        uint32_t bl[4][2] = { {bl0.x, bl0.y}, {bl0.z, bl0.w},
                              {bl1.x, bl1.y}, {bl1.z, bl1.w} };

        // A fragments: 4 m-tiles x 2 terms -> 8 lds.128
        uint4 ahv[4], alv[4];
#pragma unroll
        for (int mt = 0; mt < 4; ++mt) {
            const int mtg = wr * 4 + mt;
            ahv[mt] = *(const uint4*)(st + 0    + (mtg * 32 + lane) * 16);
            alv[mt] = *(const uint4*)(st + 4096 + (mtg * 32 + lane) * 16);
        }

#pragma unroll
        for (int mt = 0; mt < 4; ++mt) {
            const uint32_t ah[4] = { ahv[mt].x, ahv[mt].y, ahv[mt].z, ahv[mt].w };
            const uint32_t al[4] = { alv[mt].x, alv[mt].y, alv[mt].z, alv[mt].w };
#pragma unroll
            for (int nt = 0; nt < 4; ++nt) {
                mma16(macc[mt][nt], ah, bh[nt]);   // hi*hi
                mma16(macc[mt][nt], ah, bl[nt]);   // hi*lo
                mma16(macc[mt][nt], al, bh[nt]);   // lo*hi
            }
        }

        if ((i & (ACC_WINDOW - 1)) == (ACC_WINDOW - 1)) {
#pragma unroll
            for (int mt = 0; mt < 4; ++mt)
#pragma unroll
                for (int nt = 0; nt < 4; ++nt)
#pragma unroll
                    for (int r = 0; r < 4; ++r) acc[mt][nt][r] += macc[mt][nt][r];
        }
    }

    // epilogue: C fragment (m16n8 f32)
    const int r = lane >> 2, c2 = (lane & 3) * 2;
#pragma unroll
    for (int mt = 0; mt < 4; ++mt) {
#pragma unroll
        for (int nt = 0; nt < 4; ++nt) {
            const int m = by * 128 + wr * 64 + mt * 16 + r;
            const int n = bx * 128 + wc * 32 + nt * 8 + c2;
            *(float2*)&X[(size_t)m * DOUT + n] =
                make_float2(acc[mt][nt][0], acc[mt][nt][1]);
            *(float2*)&X[(size_t)(m + 8) * DOUT + n] =
                make_float2(acc[mt][nt][2], acc[mt][nt][3]);
        }
    }
}

// ---------------------------------------------------------------------------
// IF-neuron scan: mem = mem*(1-spike) + (x + bias); spike = mem > 1
// ---------------------------------------------------------------------------
__global__ void if_scan_kernel(const float* __restrict__ X,
                               const float* __restrict__ bias,
                               const float* __restrict__ mem_init,
                               float* __restrict__ out)
{
    const int idx = blockIdx.x * blockDim.x + threadIdx.x;
    const int o = idx & (DOUT - 1);
    const int b = idx >> 11;

    const float bi = bias[o];
    float mem   = mem_init[idx];
    float spike = 0.f;
    float acc   = 0.f;

#pragma unroll
    for (int t = 0; t < T_STEPS; ++t) {
        const float x = X[((size_t)t * BATCH + b) * DOUT + o] + bi;
        mem = mem * (1.f - spike) + x;
        spike = (mem > 1.f) ? 1.f : 0.f;
        acc += spike;
    }
    out[idx] = acc * (1.f / (float)T_STEPS);
}

// ---------------------------------------------------------------------------
extern "C" void kernel_launch(void* const* d_in, const int* in_sizes, int n_in,
                              void* d_out, int out_size)
{
    const float* cur_inp  = (const float*)d_in[0];  // [T, B, DIN]
    const float* weight   = (const float*)d_in[1];  // [DOUT, DIN]
    const float* bias     = (const float*)d_in[2];  // [DOUT]
    const float* mem_init = (const float*)d_in[3];  // [B, DOUT]
    float* out = (float*)d_out;                     // [B, DOUT]

    float* X;
    uint4 *Ah, *Al, *Wh, *Wl;
    cudaGetSymbolAddress((void**)&X,  g_X);
    cudaGetSymbolAddress((void**)&Ah, g_Ah);
    cudaGetSymbolAddress((void**)&Al, g_Al);
    cudaGetSymbolAddress((void**)&Wh, g_Wh);
    cudaGetSymbolAddress((void**)&Wl, g_Wl);

    cudaFuncSetAttribute(gemm_fp16x3_kernel,
                         cudaFuncAttributeMaxDynamicSharedMemorySize, SMEM_BYTES);

    // split + permute into mma fragment layout (fp16 hi/lo)
    splitA_kernel<<<(M_ROWS * DIN / 8) / 256, 256>>>(cur_inp, Ah, Al);
    splitB_kernel<<<(DOUT * DIN / 8) / 256, 256>>>(weight, Wh, Wl);

    // fp16x3 tensor-core GEMM
    dim3 grid(DOUT / 128, M_ROWS / 128);   // (16, 32)
    gemm_fp16x3_kernel<<<grid, GEMM_THREADS, SMEM_BYTES>>>(Ah, Al, Wh, Wl, X);

    // IF scan
    const int total = BATCH * DOUT;
    if_scan_kernel<<<total / 256, 256>>>(X, bias, mem_init, out);
}

// round 8
// speedup vs baseline: 2.6534x; 1.3122x over previous
#include <cuda_runtime.h>
#include <cuda_fp16.h>
#include <cstdint>

// ---------------------------------------------------------------------------
// Problem constants (fixed shapes)
// ---------------------------------------------------------------------------
#define T_STEPS 32
#define BATCH   128
#define DIN     2048
#define DOUT    2048
#define M_ROWS  (T_STEPS * BATCH)   // 4096

#define NCHUNKS16   (DIN / 16)      // 128 k16 chunks total
#define SPLITK      2
#define NC32_UNIT   (DIN / 32 / SPLITK)   // 32 chunk32s per work unit
#define GEMM_THREADS 256
#define STAGE_BYTES 32768           // Ahi 8K | Alo 8K | Bhi 8K | Blo 8K (k=32)
#define NSTAGES 3
#define SMEM_BYTES (NSTAGES * STAGE_BYTES)   // 96 KB dynamic
#define ACC_W32 4                   // flush window every 4 chunk32s (K=128)

// ---------------------------------------------------------------------------
// Device scratch
// ---------------------------------------------------------------------------
__device__ float g_X0[(size_t)M_ROWS * DOUT];
__device__ float g_X1[(size_t)M_ROWS * DOUT];
__device__ uint4 g_Ah[(size_t)M_ROWS * DIN / 8];
__device__ uint4 g_Al[(size_t)M_ROWS * DIN / 8];
__device__ uint4 g_Wh[(size_t)DOUT * DIN / 8];
__device__ uint4 g_Wl[(size_t)DOUT * DIN / 8];

// ---------------------------------------------------------------------------
// Helpers
// ---------------------------------------------------------------------------
__device__ __forceinline__ uint32_t smem_u32(const void* p) {
    uint32_t a;
    asm("{ .reg .u64 t; cvta.to.shared.u64 t, %1; cvt.u32.u64 %0, t; }"
        : "=r"(a) : "l"(p));
    return a;
}

__device__ __forceinline__ void cp16(uint32_t sm, const void* gp) {
    asm volatile("cp.async.cg.shared.global [%0], [%1], 16;"
                 :: "r"(sm), "l"(gp) : "memory");
}

__device__ __forceinline__ uint32_t pack2(float x, float y) {
    __half2 h = __floats2half2_rn(x, y);
    return *reinterpret_cast<uint32_t*>(&h);
}

__device__ __forceinline__ void mma16(float* c, const uint32_t* a,
                                      const uint32_t* b) {
    asm volatile(
        "mma.sync.aligned.m16n8k16.row.col.f32.f16.f16.f32 "
        "{%0,%1,%2,%3}, {%4,%5,%6,%7}, {%8,%9}, {%0,%1,%2,%3};"
        : "+f"(c[0]), "+f"(c[1]), "+f"(c[2]), "+f"(c[3])
        : "r"(a[0]), "r"(a[1]), "r"(a[2]), "r"(a[3]), "r"(b[0]), "r"(b[1]));
}

// ---------------------------------------------------------------------------
// Split+permute kernels: a -> hi = fp16_rn(a), lo = fp16_rn(a - hi)
// (fragment layouts identical to round 6)
// ---------------------------------------------------------------------------
__global__ void splitA_kernel(const float* __restrict__ A,
                              uint4* __restrict__ hi, uint4* __restrict__ lo) {
    const int q = blockIdx.x * blockDim.x + threadIdx.x;   // 1048576
    const int lane  = q & 31;
    const int mtg   = (q >> 5) & 7;
    const int chunk = (q >> 8) & (NCHUNKS16 - 1);
    const int mblk  = q >> 15;

    const int g = lane >> 2, tig = lane & 3;
    const int m0 = mblk * 128 + mtg * 16;
    const int k0 = chunk * 16 + tig * 2;

    const float* r0 = A + (size_t)(m0 + g) * DIN + k0;
    const float* r1 = A + (size_t)(m0 + g + 8) * DIN + k0;
    float v[8] = { r0[0], r0[1], r1[0], r1[1], r0[8], r0[9], r1[8], r1[9] };

    float h[8], l[8];
#pragma unroll
    for (int i = 0; i < 8; ++i) {
        h[i] = __half2float(__float2half_rn(v[i]));
        l[i] = v[i] - h[i];
    }
    const size_t idx = ((size_t)mblk * NCHUNKS16 + chunk) * 256 + mtg * 32 + lane;
    hi[idx] = make_uint4(pack2(h[0], h[1]), pack2(h[2], h[3]),
                         pack2(h[4], h[5]), pack2(h[6], h[7]));
    lo[idx] = make_uint4(pack2(l[0], l[1]), pack2(l[2], l[3]),
                         pack2(l[4], l[5]), pack2(l[6], l[7]));
}

__global__ void splitB_kernel(const float* __restrict__ W,
                              uint4* __restrict__ hi, uint4* __restrict__ lo) {
    const int q = blockIdx.x * blockDim.x + threadIdx.x;   // 524288
    const int lane  = q & 31;
    const int p     = (q >> 5) & 7;
    const int chunk = (q >> 8) & (NCHUNKS16 - 1);
    const int nblk  = q >> 15;

    const int g = lane >> 2, tig = lane & 3;
    const int n_a = nblk * 128 + p * 16 + g;
    const int n_b = n_a + 8;
    const int k0 = chunk * 16 + tig * 2;

    const float* ra = W + (size_t)n_a * DIN + k0;
    const float* rb = W + (size_t)n_b * DIN + k0;
    float v[8] = { ra[0], ra[1], ra[8], ra[9], rb[0], rb[1], rb[8], rb[9] };

    float h[8], l[8];
#pragma unroll
    for (int i = 0; i < 8; ++i) {
        h[i] = __half2float(__float2half_rn(v[i]));
        l[i] = v[i] - h[i];
    }
    const size_t idx = ((size_t)nblk * NCHUNKS16 + chunk) * 256 + p * 32 + lane;
    hi[idx] = make_uint4(pack2(h[0], h[1]), pack2(h[2], h[3]),
                         pack2(h[4], h[5]), pack2(h[6], h[7]));
    lo[idx] = make_uint4(pack2(l[0], l[1]), pack2(l[2], l[3]),
                         pack2(l[4], l[5]), pack2(l[6], l[7]));
}

// ---------------------------------------------------------------------------
// fp16x3 GEMM, split-K=2: unit (bx, by, bz) computes
//   Xz[m,n] = sum_{k in half z} A[m,k] * W[n,k]
// CTA tile 128x128, 8 warps, chunk32 mainloop, 3-stage cp.async pipeline.
// Windowed two-level accumulation (RZ chain bounded to K=128, RN flush).
// ---------------------------------------------------------------------------
__global__ __launch_bounds__(GEMM_THREADS, 1)
void gemm_fp16x3_kernel(const uint4* __restrict__ Ah, const uint4* __restrict__ Al,
                        const uint4* __restrict__ Bh, const uint4* __restrict__ Bl,
                        float* __restrict__ X0, float* __restrict__ X1)
{
    extern __shared__ __align__(16) char smem[];   // NSTAGES * STAGE_BYTES

    const int tid  = threadIdx.x;
    const int wid  = tid >> 5;
    const int lane = tid & 31;
    const int bx = blockIdx.x;          // N block (0..15)
    const int by = blockIdx.y;          // M block (0..31)
    const int bz = blockIdx.z;          // K half (0..1)
    const int wr = wid >> 2;            // warp row (0..1)
    const int wc = wid & 3;             // warp col (0..3)

    const uint32_t sbase = smem_u32(smem);
    const int c16base = bz * (NCHUNKS16 / SPLITK);   // 0 or 64

    // one stage = one chunk32 = 2048 x 16B:
    //   Ahi[512] Alo[512] Bhi[512] Blo[512]  (each region: 2 sub-chunk16 x 256)
    auto issue = [&](int c32, int s) {
        const uint32_t sb = sbase + (uint32_t)s * STAGE_BYTES;
        const size_t a0 = ((size_t)by * NCHUNKS16 + c16base + c32 * 2) * 256;
        const size_t b0 = ((size_t)bx * NCHUNKS16 + c16base + c32 * 2) * 256;
#pragma unroll
        for (int j = 0; j < 2; ++j) {
            const int t = tid + j * 256;
            cp16(sb + 0     + t * 16, Ah + a0 + t);
            cp16(sb + 8192  + t * 16, Al + a0 + t);
            cp16(sb + 16384 + t * 16, Bh + b0 + t);
            cp16(sb + 24576 + t * 16, Bl + b0 + t);
        }
        asm volatile("cp.async.commit_group;" ::: "memory");
    };

    float acc[4][4][4];    // master (RN adds only)
    float macc[4][4][4];   // HMMA window accumulator
#pragma unroll
    for (int i = 0; i < 4; ++i)
#pragma unroll
        for (int j = 0; j < 4; ++j)
#pragma unroll
            for (int r = 0; r < 4; ++r) acc[i][j][r] = 0.f;

    issue(0, 0);
    issue(1, 1);

    for (int i = 0; i < NC32_UNIT; ++i) {
        // ensure chunk i resident (allow only the newest group pending)
        asm volatile("cp.async.wait_group 1;" ::: "memory");
        __syncthreads();   // also: all warps finished reading stage (i+2)%3

        if (i + 2 < NC32_UNIT) issue(i + 2, (i + 2) % NSTAGES);
        else asm volatile("cp.async.commit_group;" ::: "memory");

        const char* st = smem + (i % NSTAGES) * STAGE_BYTES;

        if ((i & (ACC_W32 - 1)) == 0) {
#pragma unroll
            for (int mt = 0; mt < 4; ++mt)
#pragma unroll
                for (int nt = 0; nt < 4; ++nt)
#pragma unroll
                    for (int r = 0; r < 4; ++r) macc[mt][nt][r] = 0.f;
        }

#pragma unroll
        for (int s = 0; s < 2; ++s) {            // two k16 sub-chunks
            const char* ss = st + s * 4096;

            uint4 bh0 = *(const uint4*)(ss + 16384 + ((wc * 2 + 0) * 32 + lane) * 16);
            uint4 bh1 = *(const uint4*)(ss + 16384 + ((wc * 2 + 1) * 32 + lane) * 16);
            uint4 bl0 = *(const uint4*)(ss + 24576 + ((wc * 2 + 0) * 32 + lane) * 16);
            uint4 bl1 = *(const uint4*)(ss + 24576 + ((wc * 2 + 1) * 32 + lane) * 16);
            uint32_t bh[4][2] = { {bh0.x, bh0.y}, {bh0.z, bh0.w},
                                  {bh1.x, bh1.y}, {bh1.z, bh1.w} };
            uint32_t bl[4][2] = { {bl0.x, bl0.y}, {bl0.z, bl0.w},
                                  {bl1.x, bl1.y}, {bl1.z, bl1.w} };

            uint4 ahv[4], alv[4];
#pragma unroll
            for (int mt = 0; mt < 4; ++mt) {
                const int mtg = wr * 4 + mt;
                ahv[mt] = *(const uint4*)(ss + 0    + (mtg * 32 + lane) * 16);
                alv[mt] = *(const uint4*)(ss + 8192 + (mtg * 32 + lane) * 16);
            }

#pragma unroll
            for (int mt = 0; mt < 4; ++mt) {
                const uint32_t ah[4] = { ahv[mt].x, ahv[mt].y, ahv[mt].z, ahv[mt].w };
                const uint32_t al[4] = { alv[mt].x, alv[mt].y, alv[mt].z, alv[mt].w };
#pragma unroll
                for (int nt = 0; nt < 4; ++nt) {
                    mma16(macc[mt][nt], ah, bh[nt]);   // hi*hi
                    mma16(macc[mt][nt], ah, bl[nt]);   // hi*lo
                    mma16(macc[mt][nt], al, bh[nt]);   // lo*hi
                }
            }
        }

        if ((i & (ACC_W32 - 1)) == (ACC_W32 - 1)) {
#pragma unroll
            for (int mt = 0; mt < 4; ++mt)
#pragma unroll
                for (int nt = 0; nt < 4; ++nt)
#pragma unroll
                    for (int r = 0; r < 4; ++r) acc[mt][nt][r] += macc[mt][nt][r];
        }
    }

    // epilogue: write partial to this unit's buffer
    float* X = (bz == 0) ? X0 : X1;
    const int r = lane >> 2, c2 = (lane & 3) * 2;
#pragma unroll
    for (int mt = 0; mt < 4; ++mt) {
#pragma unroll
        for (int nt = 0; nt < 4; ++nt) {
            const int m = by * 128 + wr * 64 + mt * 16 + r;
            const int n = bx * 128 + wc * 32 + nt * 8 + c2;
            *(float2*)&X[(size_t)m * DOUT + n] =
                make_float2(acc[mt][nt][0], acc[mt][nt][1]);
            *(float2*)&X[(size_t)(m + 8) * DOUT + n] =
                make_float2(acc[mt][nt][2], acc[mt][nt][3]);
        }
    }
}

// ---------------------------------------------------------------------------
// IF-neuron scan with split-K reduction:
//   x = X0 + X1 + bias; mem = mem*(1-spike) + x; spike = mem > 1
// ---------------------------------------------------------------------------
__global__ void if_scan_kernel(const float* __restrict__ X0,
                               const float* __restrict__ X1,
                               const float* __restrict__ bias,
                               const float* __restrict__ mem_init,
                               float* __restrict__ out)
{
    const int idx = blockIdx.x * blockDim.x + threadIdx.x;
    const int o = idx & (DOUT - 1);
    const int b = idx >> 11;

    const float bi = bias[o];
    float mem   = mem_init[idx];
    float spike = 0.f;
    float acc   = 0.f;

#pragma unroll
    for (int t = 0; t < T_STEPS; ++t) {
        const size_t p = ((size_t)t * BATCH + b) * DOUT + o;
        const float x = X0[p] + X1[p] + bi;
        mem = mem * (1.f - spike) + x;
        spike = (mem > 1.f) ? 1.f : 0.f;
        acc += spike;
    }
    out[idx] = acc * (1.f / (float)T_STEPS);
}

// ---------------------------------------------------------------------------
extern "C" void kernel_launch(void* const* d_in, const int* in_sizes, int n_in,
                              void* d_out, int out_size)
{
    const float* cur_inp  = (const float*)d_in[0];  // [T, B, DIN]
    const float* weight   = (const float*)d_in[1];  // [DOUT, DIN]
    const float* bias     = (const float*)d_in[2];  // [DOUT]
    const float* mem_init = (const float*)d_in[3];  // [B, DOUT]
    float* out = (float*)d_out;                     // [B, DOUT]

    float *X0, *X1;
    uint4 *Ah, *Al, *Wh, *Wl;
    cudaGetSymbolAddress((void**)&X0, g_X0);
    cudaGetSymbolAddress((void**)&X1, g_X1);
    cudaGetSymbolAddress((void**)&Ah, g_Ah);
    cudaGetSymbolAddress((void**)&Al, g_Al);
    cudaGetSymbolAddress((void**)&Wh, g_Wh);
    cudaGetSymbolAddress((void**)&Wl, g_Wl);

    cudaFuncSetAttribute(gemm_fp16x3_kernel,
                         cudaFuncAttributeMaxDynamicSharedMemorySize, SMEM_BYTES);

    // split + permute into mma fragment layout (fp16 hi/lo)
    splitA_kernel<<<(M_ROWS * DIN / 8) / 256, 256>>>(cur_inp, Ah, Al);
    splitB_kernel<<<(DOUT * DIN / 8) / 256, 256>>>(weight, Wh, Wl);

    // fp16x3 tensor-core GEMM, split-K = 2
    dim3 grid(DOUT / 128, M_ROWS / 128, SPLITK);   // (16, 32, 2)
    gemm_fp16x3_kernel<<<grid, GEMM_THREADS, SMEM_BYTES>>>(Ah, Al, Wh, Wl, X0, X1);

    // IF scan + split-K reduction
    const int total = BATCH * DOUT;
    if_scan_kernel<<<total / 256, 256>>>(X0, X1, bias, mem_init, out);
}

// round 11
// speedup vs baseline: 2.6706x; 1.0065x over previous
#include <cuda_runtime.h>
#include <cuda_fp16.h>
#include <cstdint>

// ---------------------------------------------------------------------------
// Problem constants (fixed shapes)
// ---------------------------------------------------------------------------
#define T_STEPS 32
#define BATCH   128
#define DIN     2048
#define DOUT    2048
#define M_ROWS  (T_STEPS * BATCH)   // 4096

#define NCHUNKS16   (DIN / 16)      // 128 k16 chunks total
#define SPLITK      2
#define NC32_UNIT   (DIN / 32 / SPLITK)   // 32 chunk32s per work unit
#define GEMM_THREADS 256            // 8 warps; 2 CTAs/SM -> 4 warps/SMSP
#define STAGE_BYTES 24576           // Ah 8K | Al 8K | Bh 4K | Bl 4K (k=32, N=64)
#define NSTAGES 3
#define SMEM_BYTES (NSTAGES * STAGE_BYTES)   // 72 KB dynamic (x2 CTAs = 144 KB/SM)
#define ACC_W32 4                   // flush window every 4 chunk32s (K=128)

// stage region offsets
#define OFF_AH 0
#define OFF_AL 8192
#define OFF_BH 16384
#define OFF_BL 20480

// ---------------------------------------------------------------------------
// Device scratch
// ---------------------------------------------------------------------------
__device__ float g_X0[(size_t)M_ROWS * DOUT];
__device__ float g_X1[(size_t)M_ROWS * DOUT];
__device__ uint4 g_Ah[(size_t)M_ROWS * DIN / 8];
__device__ uint4 g_Al[(size_t)M_ROWS * DIN / 8];
__device__ uint4 g_Wh[(size_t)DOUT * DIN / 8];
__device__ uint4 g_Wl[(size_t)DOUT * DIN / 8];

// ---------------------------------------------------------------------------
// Helpers
// ---------------------------------------------------------------------------
__device__ __forceinline__ uint32_t smem_u32(const void* p) {
    uint32_t a;
    asm("{ .reg .u64 t; cvta.to.shared.u64 t, %1; cvt.u32.u64 %0, t; }"
        : "=r"(a) : "l"(p));
    return a;
}

__device__ __forceinline__ void cp16(uint32_t sm, const void* gp) {
    asm volatile("cp.async.cg.shared.global [%0], [%1], 16;"
                 :: "r"(sm), "l"(gp) : "memory");
}

__device__ __forceinline__ uint32_t pack2(float x, float y) {
    __half2 h = __floats2half2_rn(x, y);
    return *reinterpret_cast<uint32_t*>(&h);
}

__device__ __forceinline__ void mma16(float* c, const uint32_t* a,
                                      const uint32_t* b) {
    asm volatile(
        "mma.sync.aligned.m16n8k16.row.col.f32.f16.f16.f32 "
        "{%0,%1,%2,%3}, {%4,%5,%6,%7}, {%8,%9}, {%0,%1,%2,%3};"
        : "+f"(c[0]), "+f"(c[1]), "+f"(c[2]), "+f"(c[3])
        : "r"(a[0]), "r"(a[1]), "r"(a[2]), "r"(a[3]), "r"(b[0]), "r"(b[1]));
}

// ---------------------------------------------------------------------------
// Split+permute kernels: a -> hi = fp16_rn(a), lo = fp16_rn(a - hi)
// (fragment layouts identical to rounds 6-8)
// ---------------------------------------------------------------------------
__global__ void splitA_kernel(const float* __restrict__ A,
                              uint4* __restrict__ hi, uint4* __restrict__ lo) {
    const int q = blockIdx.x * blockDim.x + threadIdx.x;   // 1048576
    const int lane  = q & 31;
    const int mtg   = (q >> 5) & 7;
    const int chunk = (q >> 8) & (NCHUNKS16 - 1);
    const int mblk  = q >> 15;

    const int g = lane >> 2, tig = lane & 3;
    const int m0 = mblk * 128 + mtg * 16;
    const int k0 = chunk * 16 + tig * 2;

    const float* r0 = A + (size_t)(m0 + g) * DIN + k0;
    const float* r1 = A + (size_t)(m0 + g + 8) * DIN + k0;
    float v[8] = { r0[0], r0[1], r1[0], r1[1], r0[8], r0[9], r1[8], r1[9] };

    float h[8], l[8];
#pragma unroll
    for (int i = 0; i < 8; ++i) {
        h[i] = __half2float(__float2half_rn(v[i]));
        l[i] = v[i] - h[i];
    }
    const size_t idx = ((size_t)mblk * NCHUNKS16 + chunk) * 256 + mtg * 32 + lane;
    hi[idx] = make_uint4(pack2(h[0], h[1]), pack2(h[2], h[3]),
                         pack2(h[4], h[5]), pack2(h[6], h[7]));
    lo[idx] = make_uint4(pack2(l[0], l[1]), pack2(l[2], l[3]),
                         pack2(l[4], l[5]), pack2(l[6], l[7]));
}

__global__ void splitB_kernel(const float* __restrict__ W,
                              uint4* __restrict__ hi, uint4* __restrict__ lo) {
    const int q = blockIdx.x * blockDim.x + threadIdx.x;   // 524288
    const int lane  = q & 31;
    const int p     = (q >> 5) & 7;
    const int chunk = (q >> 8) & (NCHUNKS16 - 1);
    const int nblk  = q >> 15;

    const int g = lane >> 2, tig = lane & 3;
    const int n_a = nblk * 128 + p * 16 + g;
    const int n_b = n_a + 8;
    const int k0 = chunk * 16 + tig * 2;

    const float* ra = W + (size_t)n_a * DIN + k0;
    const float* rb = W + (size_t)n_b * DIN + k0;
    float v[8] = { ra[0], ra[1], ra[8], ra[9], rb[0], rb[1], rb[8], rb[9] };

    float h[8], l[8];
#pragma unroll
    for (int i = 0; i < 8; ++i) {
        h[i] = __half2float(__float2half_rn(v[i]));
        l[i] = v[i] - h[i];
    }
    const size_t idx = ((size_t)nblk * NCHUNKS16 + chunk) * 256 + p * 32 + lane;
    hi[idx] = make_uint4(pack2(h[0], h[1]), pack2(h[2], h[3]),
                         pack2(h[4], h[5]), pack2(h[6], h[7]));
    lo[idx] = make_uint4(pack2(l[0], l[1]), pack2(l[2], l[3]),
                         pack2(l[4], l[5]), pack2(l[6], l[7]));
}

// ---------------------------------------------------------------------------
// fp16x3 GEMM, split-K=2, CTA tile 128x64, 8 warps (warp tile 64x16),
// 2 CTAs/SM (4 warps/SMSP with independent barriers):
//   Xz[m,n] = sum_{k in half z} A[m,k] * W[n,k]
// chunk32 mainloop, 3-stage cp.async pipeline.
// Windowed two-level accumulation (RZ chain bounded to K=128, RN flush).
// ---------------------------------------------------------------------------
__global__ __launch_bounds__(GEMM_THREADS, 2)
void gemm_fp16x3_kernel(const uint4* __restrict__ Ah, const uint4* __restrict__ Al,
                        const uint4* __restrict__ Bh, const uint4* __restrict__ Bl,
                        float* __restrict__ X0, float* __restrict__ X1)
{
    extern __shared__ __align__(16) char smem[];   // NSTAGES * STAGE_BYTES

    const int tid  = threadIdx.x;
    const int wid  = tid >> 5;
    const int lane = tid & 31;
    const int bx = blockIdx.x;          // N block (0..31), 64 cols each
    const int by = blockIdx.y;          // M block (0..31)
    const int bz = blockIdx.z;          // K half (0..1)
    const int wr = wid >> 2;            // warp row (0..1)  -> 64 M-rows
    const int wc = wid & 3;             // warp col (0..3)  -> 16 N-cols

    const uint32_t sbase = smem_u32(smem);
    const int c16base = bz * (NCHUNKS16 / SPLITK);   // 0 or 64
    const int nblk = bx >> 1;           // 128-wide B layout block
    const int nhalf = bx & 1;           // which 64-slice of it

    // one stage = one chunk32: A 1024 uint4 (2 chunk16 x 512), B 512 uint4
    // (2 chunk16 x 256-half-regions). 6 cp.async per thread.
    auto issue = [&](int c32, int s) {
        const uint32_t sb = sbase + (uint32_t)s * STAGE_BYTES;
        const size_t a0 = ((size_t)by * NCHUNKS16 + c16base + c32 * 2) * 256;
        const size_t b0 = ((size_t)nblk * NCHUNKS16 + c16base + c32 * 2) * 256
                        + (size_t)nhalf * 128;
#pragma unroll
        for (int j = 0; j < 2; ++j) {
            const int t = tid + j * 256;
            cp16(sb + OFF_AH + t * 16, Ah + a0 + t);
            cp16(sb + OFF_AL + t * 16, Al + a0 + t);
        }
        {
            const int sub = tid >> 7;          // chunk16 index 0/1
            const int off = tid & 127;
            const size_t bsrc = b0 + (size_t)sub * 256 + off;
            cp16(sb + OFF_BH + tid * 16, Bh + bsrc);
            cp16(sb + OFF_BL + tid * 16, Bl + bsrc);
        }
        asm volatile("cp.async.commit_group;" ::: "memory");
    };

    float acc[4][2][4];    // master (RN adds only)
    float macc[4][2][4];   // HMMA window accumulator
#pragma unroll
    for (int i = 0; i < 4; ++i)
#pragma unroll
        for (int j = 0; j < 2; ++j)
#pragma unroll
            for (int r = 0; r < 4; ++r) acc[i][j][r] = 0.f;

    issue(0, 0);
    issue(1, 1);

    for (int i = 0; i < NC32_UNIT; ++i) {
        asm volatile("cp.async.wait_group 1;" ::: "memory");
        __syncthreads();

        if (i + 2 < NC32_UNIT) issue(i + 2, (i + 2) % NSTAGES);
        else asm volatile("cp.async.commit_group;" ::: "memory");

        const char* st = smem + (i % NSTAGES) * STAGE_BYTES;

        if ((i & (ACC_W32 - 1)) == 0) {
#pragma unroll
            for (int mt = 0; mt < 4; ++mt)
#pragma unroll
                for (int nt = 0; nt < 2; ++nt)
#pragma unroll
                    for (int r = 0; r < 4; ++r) macc[mt][nt][r] = 0.f;
        }

#pragma unroll
        for (int s = 0; s < 2; ++s) {            // two k16 sub-chunks
            // B fragments: one n-tile pair per warp (ntg = 2wc, 2wc+1)
            uint4 bhv = *(const uint4*)(st + OFF_BH + s * 2048 + (wc * 32 + lane) * 16);
            uint4 blv = *(const uint4*)(st + OFF_BL + s * 2048 + (wc * 32 + lane) * 16);
            const uint32_t* bhp = (const uint32_t*)&bhv;   // [0,1]=nt0, [2,3]=nt1
            const uint32_t* blp = (const uint32_t*)&blv;

            // A fragments: 4 m-tiles x 2 terms
            uint4 ahv[4], alv[4];
#pragma unroll
            for (int mt = 0; mt < 4; ++mt) {
                const int mtg = wr * 4 + mt;
                ahv[mt] = *(const uint4*)(st + OFF_AH + s * 4096 + (mtg * 32 + lane) * 16);
                alv[mt] = *(const uint4*)(st + OFF_AL + s * 4096 + (mtg * 32 + lane) * 16);
            }

#pragma unroll
            for (int mt = 0; mt < 4; ++mt) {
                const uint32_t* ah = (const uint32_t*)&ahv[mt];
                const uint32_t* al = (const uint32_t*)&alv[mt];
#pragma unroll
                for (int nt = 0; nt < 2; ++nt) {
                    mma16(macc[mt][nt], ah, bhp + 2 * nt);   // hi*hi
                    mma16(macc[mt][nt], ah, blp + 2 * nt);   // hi*lo
                    mma16(macc[mt][nt], al, bhp + 2 * nt);   // lo*hi
                }
            }
        }

        if ((i & (ACC_W32 - 1)) == (ACC_W32 - 1)) {
#pragma unroll
            for (int mt = 0; mt < 4; ++mt)
#pragma unroll
                for (int nt = 0; nt < 2; ++nt)
#pragma unroll
                    for (int r = 0; r < 4; ++r) acc[mt][nt][r] += macc[mt][nt][r];
        }
    }

    // epilogue: write partial to this unit's buffer
    float* X = (bz == 0) ? X0 : X1;
    const int r = lane >> 2, c2 = (lane & 3) * 2;
#pragma unroll
    for (int mt = 0; mt < 4; ++mt) {
#pragma unroll
        for (int nt = 0; nt < 2; ++nt) {
            const int m = by * 128 + wr * 64 + mt * 16 + r;
            const int n = bx * 64 + wc * 16 + nt * 8 + c2;
            *(float2*)&X[(size_t)m * DOUT + n] =
                make_float2(acc[mt][nt][0], acc[mt][nt][1]);
            *(float2*)&X[(size_t)(m + 8) * DOUT + n] =
                make_float2(acc[mt][nt][2], acc[mt][nt][3]);
        }
    }
}

// ---------------------------------------------------------------------------
// IF-neuron scan with split-K reduction:
//   x = X0 + X1 + bias; mem = mem*(1-spike) + x; spike = mem > 1
// ---------------------------------------------------------------------------
__global__ void if_scan_kernel(const float* __restrict__ X0,
                               const float* __restrict__ X1,
                               const float* __restrict__ bias,
                               const float* __restrict__ mem_init,
                               float* __restrict__ out)
{
    const int idx = blockIdx.x * blockDim.x + threadIdx.x;
    const int o = idx & (DOUT - 1);
    const int b = idx >> 11;

    const float bi = bias[o];
    float mem   = mem_init[idx];
    float spike = 0.f;
    float acc   = 0.f;

#pragma unroll
    for (int t = 0; t < T_STEPS; ++t) {
        const size_t p = ((size_t)t * BATCH + b) * DOUT + o;
        const float x = X0[p] + X1[p] + bi;
        mem = mem * (1.f - spike) + x;
        spike = (mem > 1.f) ? 1.f : 0.f;
        acc += spike;
    }
    out[idx] = acc * (1.f / (float)T_STEPS);
}

// ---------------------------------------------------------------------------
extern "C" void kernel_launch(void* const* d_in, const int* in_sizes, int n_in,
                              void* d_out, int out_size)
{
    const float* cur_inp  = (const float*)d_in[0];  // [T, B, DIN]
    const float* weight   = (const float*)d_in[1];  // [DOUT, DIN]
    const float* bias     = (const float*)d_in[2];  // [DOUT]
    const float* mem_init = (const float*)d_in[3];  // [B, DOUT]
    float* out = (float*)d_out;                     // [B, DOUT]

    float *X0, *X1;
    uint4 *Ah, *Al, *Wh, *Wl;
    cudaGetSymbolAddress((void**)&X0, g_X0);
    cudaGetSymbolAddress((void**)&X1, g_X1);
    cudaGetSymbolAddress((void**)&Ah, g_Ah);
    cudaGetSymbolAddress((void**)&Al, g_Al);
    cudaGetSymbolAddress((void**)&Wh, g_Wh);
    cudaGetSymbolAddress((void**)&Wl, g_Wl);

    cudaFuncSetAttribute(gemm_fp16x3_kernel,
                         cudaFuncAttributeMaxDynamicSharedMemorySize, SMEM_BYTES);

    // split + permute into mma fragment layout (fp16 hi/lo)
    splitA_kernel<<<(M_ROWS * DIN / 8) / 256, 256>>>(cur_inp, Ah, Al);
    splitB_kernel<<<(DOUT * DIN / 8) / 256, 256>>>(weight, Wh, Wl);

    // fp16x3 tensor-core GEMM, split-K = 2, CTA tile 128x64, 2 CTAs/SM
    dim3 grid(DOUT / 64, M_ROWS / 128, SPLITK);   // (32, 32, 2)
    gemm_fp16x3_kernel<<<grid, GEMM_THREADS, SMEM_BYTES>>>(Ah, Al, Wh, Wl, X0, X1);

    // IF scan + split-K reduction
    const int total = BATCH * DOUT;
    if_scan_kernel<<<total / 256, 256>>>(X0, X1, bias, mem_init, out);
}